// round 4
// baseline (speedup 1.0000x reference)
#include <cuda_runtime.h>
#include <math.h>

// Problem constants
#define BSX   2
#define QL    64
#define KLN   64
#define NH    8
#define DKV   64
#define INNER 512
#define VOC   4096
#define NBH   16          // BSX * NH
#define VSPL  8           // v-range splits for argmax kernel

// Masks (all scratch arrays are power-of-2 element counts)
#define M_PROJ 0xFFFFu     // 65536
#define M_DICT 0x3FFFFu    // 262144
#define M_AB   0x3FFFFFu   // 4194304
#define M_NRM  0x3FFu      // 1024
#define M_G    0xFFFFu     // 65536
#define M_P    0x7FFFFu    // 524288

// ---------------- scratch (device globals; no allocation allowed) -------------
__device__ float g_qproj[BSX * QL * INNER];        // [b][q][e]       65536
__device__ float g_kproj[BSX * KLN * INNER];       // [b][k][e]       65536
__device__ float g_dn[VOC * DKV];                  // l2-norm dict    262144
__device__ float g_dp[VOC * DKV];                  // LN(dict)@O      262144
__device__ float g_A[NBH * QL * VOC];              // [bh][q][v]      4194304
__device__ float g_Bm[NBH * KLN * VOC];            // [bh][k][v]      4194304
__device__ float g_nq[NBH * QL];                   // ||qp||^2        1024
__device__ float g_nk[NBH * KLN];                  //                 1024
__device__ float g_G[NBH * QL * KLN];              // <qp,kp>         65536
__device__ float g_pv[NBH * QL * KLN * VSPL];      // partial max     524288
__device__ int   g_pi[NBH * QL * KLN * VSPL];      // partial argidx  524288

// ---------------- K0: dict preprocessing (l2norm + LN@O) ----------------------
__global__ void k0_dict(const float* __restrict__ dict,
                        const float* __restrict__ vg,
                        const float* __restrict__ vb,
                        const float* __restrict__ O) {
    int l = threadIdx.x;                               // 0..31
    int r = blockIdx.x * blockDim.y + threadIdx.y;     // 0..4095
    float x0 = dict[(r * DKV + l) & M_DICT];
    float x1 = dict[(r * DKV + 32 + l) & M_DICT];

    float s = x0 * x0 + x1 * x1;
    #pragma unroll
    for (int o = 16; o > 0; o >>= 1) s += __shfl_xor_sync(0xffffffffu, s, o);
    float inv = rsqrtf(fmaxf(s, 1e-12f));
    g_dn[(r * DKV + l) & M_DICT]      = x0 * inv;
    g_dn[(r * DKV + 32 + l) & M_DICT] = x1 * inv;

    float m = x0 + x1;
    #pragma unroll
    for (int o = 16; o > 0; o >>= 1) m += __shfl_xor_sync(0xffffffffu, m, o);
    m *= (1.0f / 64.0f);
    float d0 = x0 - m, d1 = x1 - m;
    float v = d0 * d0 + d1 * d1;
    #pragma unroll
    for (int o = 16; o > 0; o >>= 1) v += __shfl_xor_sync(0xffffffffu, v, o);
    v *= (1.0f / 64.0f);
    float rs = rsqrtf(v + 1e-6f);
    float ln0 = d0 * rs * vg[l & 63]      + vb[l & 63];
    float ln1 = d1 * rs * vg[(l + 32) & 63] + vb[(l + 32) & 63];

    float a0 = 0.f, a1 = 0.f;
    #pragma unroll
    for (int d2 = 0; d2 < 32; d2++) {
        float t = __shfl_sync(0xffffffffu, ln0, d2);
        a0 += t * O[(d2 * 64 + l) & 4095];
        a1 += t * O[(d2 * 64 + 32 + l) & 4095];
    }
    #pragma unroll
    for (int d2 = 0; d2 < 32; d2++) {
        float t = __shfl_sync(0xffffffffu, ln1, d2);
        a0 += t * O[((32 + d2) * 64 + l) & 4095];
        a1 += t * O[((32 + d2) * 64 + 32 + l) & 4095];
    }
    g_dp[(r * DKV + l) & M_DICT]      = a0;
    g_dp[(r * DKV + 32 + l) & M_DICT] = a1;
}

// ---------------- K1: q_proj / k_proj GEMM ------------------------------------
__global__ void k1_proj(const float* __restrict__ q, const float* __restrict__ k,
                        const float* __restrict__ qpe, const float* __restrict__ kpe,
                        const float* __restrict__ wi) {
    __shared__ float xs[8][INNER];
    int side = blockIdx.z;
    const float* xin = side ? k   : q;
    const float* pin = side ? kpe : qpe;
    const float* W   = wi + side * (INNER * INNER);
    float* out = side ? g_kproj : g_qproj;
    int m0 = blockIdx.y * 8;
    int tid = threadIdx.x;                             // 128 threads
    for (int i = tid; i < 8 * INNER; i += 128) {
        int r = i >> 9, d = i & 511;
        int gidx = ((m0 + r) * INNER + d) & M_PROJ;
        xs[r][d] = xin[gidx] + pin[gidx];
    }
    __syncthreads();
    int e = blockIdx.x * 128 + tid;                    // 0..511
    float acc[8] = {};
    for (int d = 0; d < INNER; d += 2) {
        float w0 = W[((d + 0) * INNER + e) & 0x3FFFF];
        float w1 = W[((d + 1) * INNER + e) & 0x3FFFF];
        #pragma unroll
        for (int r = 0; r < 8; r++) {
            acc[r] += xs[r][d] * w0 + xs[r][d + 1] * w1;
        }
    }
    #pragma unroll
    for (int r = 0; r < 8; r++)
        out[((m0 + r) * INNER + e) & M_PROJ] = acc[r];
}

// ---------------- K1c: per-head Gram matrix + row norms -----------------------
__global__ void k1c_gram() {
    __shared__ float qs[64][65];
    __shared__ float ks[64][65];
    int bh = blockIdx.x;                               // 0..15
    int b = bh >> 3, h = bh & 7;
    int tid = threadIdx.x;                             // 256
    for (int i = tid; i < 4096; i += 256) {
        int r = i >> 6, d = i & 63;
        qs[r][d] = g_qproj[((b * 64 + r) * INNER + h * 64 + d) & M_PROJ];
        ks[r][d] = g_kproj[((b * 64 + r) * INNER + h * 64 + d) & M_PROJ];
    }
    __syncthreads();
    int qq = tid >> 2;
    int kb = (tid & 3) * 16;
    float acc[16] = {};
    for (int d = 0; d < 64; d++) {
        float a = qs[qq][d];
        #pragma unroll
        for (int j = 0; j < 16; j++) acc[j] += a * ks[kb + j][d];
    }
    #pragma unroll
    for (int j = 0; j < 16; j++)
        g_G[((bh * 64 + qq) * 64 + kb + j) & M_G] = acc[j];
    if (tid < 64) {
        float s = 0.f;
        #pragma unroll 8
        for (int d = 0; d < 64; d++) { float x = qs[tid][d]; s += x * x; }
        g_nq[(bh * 64 + tid) & M_NRM] = s;
    } else if (tid < 128) {
        int r = tid - 64;
        float s = 0.f;
        #pragma unroll 8
        for (int d = 0; d < 64; d++) { float x = ks[r][d]; s += x * x; }
        g_nk[(bh * 64 + r) & M_NRM] = s;
    }
}

// ---------------- K2: A = qp_head @ d_n^T, B = kp_head @ d_n^T ----------------
__global__ void k2_ab() {
    __shared__ float xs[32][65];
    __shared__ float dst[64][129];                     // [d][v] transposed
    int side = blockIdx.z;
    int bh = blockIdx.y >> 1, rt = blockIdx.y & 1;
    int b = bh >> 3, h = bh & 7;
    int v0 = blockIdx.x * 128;
    const float* xin = side ? g_kproj : g_qproj;
    float* out = side ? g_Bm : g_A;
    int tid = threadIdx.x;                             // 256
    for (int i = tid; i < 32 * 64; i += 256) {
        int r = i >> 6, d = i & 63;
        xs[r][d] = xin[((b * 64 + rt * 32 + r) * INNER + h * 64 + d) & M_PROJ];
    }
    for (int i = tid; i < 128 * 64; i += 256) {
        int vl = i >> 6, d = i & 63;
        dst[d][vl] = g_dn[((v0 + vl) * DKV + d) & M_DICT];
    }
    __syncthreads();
    int tv = tid & 31, tr = tid >> 5;                  // 32 v-groups x 8 row-groups
    float acc[4][4] = {};
    #pragma unroll 2
    for (int d = 0; d < 64; d++) {
        float d0 = dst[d][tv * 4 + 0];
        float d1 = dst[d][tv * 4 + 1];
        float d2 = dst[d][tv * 4 + 2];
        float d3 = dst[d][tv * 4 + 3];
        #pragma unroll
        for (int i = 0; i < 4; i++) {
            float a = xs[tr * 4 + i][d];
            acc[i][0] += a * d0; acc[i][1] += a * d1;
            acc[i][2] += a * d2; acc[i][3] += a * d3;
        }
    }
    #pragma unroll
    for (int i = 0; i < 4; i++) {
        int row = rt * 32 + tr * 4 + i;
        int base = (bh * 64 + row) * VOC + v0 + tv * 4;
        out[(base + 0) & M_AB] = acc[i][0];
        out[(base + 1) & M_AB] = acc[i][1];
        out[(base + 2) & M_AB] = acc[i][2];
        out[(base + 3) & M_AB] = acc[i][3];
    }
}

// ---------------- K3: partial argmax_v (A[q,v] + B[k,v]) ----------------------
__global__ void k3_argmax() {
    __shared__ float As[32][129];
    __shared__ float Bs[32][129];
    int vs = blockIdx.x;                               // 0..7
    int qt = blockIdx.y >> 1, kt = blockIdx.y & 1;
    int bh = blockIdx.z;
    int tid = threadIdx.x;                             // 256
    int tq = tid & 15, tk = tid >> 4;
    float best[2][2];
    int   bidx[2][2];
    #pragma unroll
    for (int i = 0; i < 2; i++)
        #pragma unroll
        for (int j = 0; j < 2; j++) { best[i][j] = -3.402823466e38f; bidx[i][j] = 0; }
    int q0 = qt * 32, k0 = kt * 32;
    for (int sc = 0; sc < 4; sc++) {
        int vb = vs * 512 + sc * 128;
        __syncthreads();
        for (int i = tid; i < 4096; i += 256) {
            int r = i >> 7, v = i & 127;
            As[r][v] = g_A [((bh * 64 + q0 + r) * VOC + vb + v) & M_AB];
            Bs[r][v] = g_Bm[((bh * 64 + k0 + r) * VOC + vb + v) & M_AB];
        }
        __syncthreads();
        #pragma unroll 4
        for (int v = 0; v < 128; v++) {
            float a0 = As[2 * tq][v],     a1 = As[2 * tq + 1][v];
            float b0 = Bs[2 * tk][v],     b1 = Bs[2 * tk + 1][v];
            int gi = vb + v;
            float c;
            c = a0 + b0; if (c > best[0][0]) { best[0][0] = c; bidx[0][0] = gi; }
            c = a0 + b1; if (c > best[0][1]) { best[0][1] = c; bidx[0][1] = gi; }
            c = a1 + b0; if (c > best[1][0]) { best[1][0] = c; bidx[1][0] = gi; }
            c = a1 + b1; if (c > best[1][1]) { best[1][1] = c; bidx[1][1] = gi; }
        }
    }
    #pragma unroll
    for (int i = 0; i < 2; i++)
        #pragma unroll
        for (int j = 0; j < 2; j++) {
            int q = q0 + 2 * tq + i, kk = k0 + 2 * tk + j;
            int pair = (bh * 64 + q) * 64 + kk;
            g_pv[(pair * VSPL + vs) & M_P] = best[i][j];
            g_pi[(pair * VSPL + vs) & M_P] = bidx[i][j];
        }
}

// ---------------- K4: merge partials + scores/ids + weighted sum + final LN ---
__global__ void k4_final(const float* __restrict__ lng, const float* __restrict__ lnb,
                         float* __restrict__ out, int n_out) {
    __shared__ float sws[64];
    __shared__ int   sid[64];
    __shared__ float sred[64];
    int idx = blockIdx.x;                              // 0..1023 = (b,q,h)
    int b = idx >> 9, q = (idx >> 3) & 63, h = idx & 7;
    int bh = b * 8 + h;
    int t = threadIdx.x;                               // 64
    int kk = t;
    int pair = (bh * 64 + q) * 64 + kk;
    float bv = -3.402823466e38f; int bi = 0;
    #pragma unroll
    for (int p = 0; p < VSPL; p++) {                   // ascending v-order: first-max
        float v = g_pv[(pair * VSPL + p) & M_P];
        if (v > bv) { bv = v; bi = g_pi[(pair * VSPL + p) & M_P]; }
    }
    float n2 = g_nq[(bh * 64 + q) & M_NRM] + g_nk[(bh * 64 + kk) & M_NRM]
             + 2.0f * g_G[((bh * 64 + q) * 64 + kk) & M_G];
    float ws = bv * rsqrtf(fmaxf(n2, 1e-12f));
    int oidx = ((b * 64 + q) * 64 + kk) * 8 + h;
    if (65536 + oidx < n_out)  out[65536  + oidx] = (float)bi;  // out_ids
    if (131072 + oidx < n_out) out[131072 + oidx] = ws;         // r3_scores
    sws[t] = ws; sid[t] = bi;
    __syncthreads();
    int e = t;
    float acc = 0.f;
    #pragma unroll 4
    for (int j = 0; j < 64; j++)
        acc += sws[j] * g_dp[(sid[j] * DKV + e) & M_DICT];
    acc *= (1.0f / 64.0f);
    sred[t] = acc; __syncthreads();
    #pragma unroll
    for (int s = 32; s > 0; s >>= 1) { if (t < s) sred[t] += sred[t + s]; __syncthreads(); }
    float mean = sred[0] * (1.0f / 64.0f);
    __syncthreads();
    float diff = acc - mean;
    sred[t] = diff * diff; __syncthreads();
    #pragma unroll
    for (int s = 32; s > 0; s >>= 1) { if (t < s) sred[t] += sred[t + s]; __syncthreads(); }
    float var = sred[0] * (1.0f / 64.0f);
    float r = diff * rsqrtf(var + 1e-6f) * lng[e & 63] + lnb[e & 63];
    int widx = (bh * 64 + q) * 64 + e;
    if (widx < n_out) out[widx] = r;                   // [b][h][q][e]
}

// ---------------- fallback: zero-fill output (diagnostic, never crashes) ------
__global__ void kz_zero(float* __restrict__ out, int n_out) {
    int i = blockIdx.x * 256 + threadIdx.x;
    if (i < n_out) out[i] = 0.0f;
}

// ---------------- launch ------------------------------------------------------
static bool size_ok(int got, int need_elems) {
    return got == need_elems || got == need_elems * 4;   // elements or bytes
}

extern "C" void kernel_launch(void* const* d_in, const int* in_sizes, int n_in,
                              void* d_out, int out_size) {
    // Normalize out_size to elements (legit element counts: 65536 or 196608)
    int n_out = out_size;
    if (n_out == 65536 * 4 || n_out == 196608 * 4) n_out >>= 2;
    if (n_out < 0) n_out = 0;
    float* out = (float*)d_out;

    const int SZ_BIG = BSX * QL * INNER;       // 65536
    const int SZ_WI  = 2 * INNER * INNER;      // 524288
    const int SZ_DI  = VOC * DKV;              // 262144
    const int SZ_OW  = DKV * DKV;              // 4096
    const int SZ_V   = DKV;                    // 64

    const float *query = 0, *key = 0, *qpe = 0, *kpe = 0, *wi = 0, *dict = 0,
                *ow = 0, *vg = 0, *vb = 0, *lg = 0, *lb = 0;
    bool mapped = false;

    if (n_in >= 11) {
        // Try signature order: query,key,qpe,kpe,wi,dict,vq_ln_g,vq_ln_b,ow,ln_g,ln_b
        const int sig[11] = {SZ_BIG, SZ_BIG, SZ_BIG, SZ_BIG, SZ_WI, SZ_DI,
                             SZ_V, SZ_V, SZ_OW, SZ_V, SZ_V};
        bool ok = true;
        for (int i = 0; i < 11; i++) ok = ok && size_ok(in_sizes[i], sig[i]);
        if (ok) {
            query = (const float*)d_in[0];  key = (const float*)d_in[1];
            qpe   = (const float*)d_in[2];  kpe = (const float*)d_in[3];
            wi    = (const float*)d_in[4];  dict = (const float*)d_in[5];
            vg    = (const float*)d_in[6];  vb  = (const float*)d_in[7];
            ow    = (const float*)d_in[8];  lg  = (const float*)d_in[9];
            lb    = (const float*)d_in[10];
            mapped = true;
        }
        if (!mapped) {
            // Alphabetical: key,k_pe,ln_b,ln_g,q_pe,query,vq_dict,vq_ln_b,vq_ln_g,vq_o_w,wi_w
            const int alp[11] = {SZ_BIG, SZ_BIG, SZ_V, SZ_V, SZ_BIG, SZ_BIG,
                                 SZ_DI, SZ_V, SZ_V, SZ_OW, SZ_WI};
            bool ok2 = true;
            for (int i = 0; i < 11; i++) ok2 = ok2 && size_ok(in_sizes[i], alp[i]);
            if (ok2) {
                key  = (const float*)d_in[0];  kpe = (const float*)d_in[1];
                lb   = (const float*)d_in[2];  lg  = (const float*)d_in[3];
                qpe  = (const float*)d_in[4];  query = (const float*)d_in[5];
                dict = (const float*)d_in[6];  vb  = (const float*)d_in[7];
                vg   = (const float*)d_in[8];  ow  = (const float*)d_in[9];
                wi   = (const float*)d_in[10];
                mapped = true;
            }
        }
    }

    if (!mapped) {
        // Diagnostic fallback: bounded zero-fill, no unverified dereference.
        if (n_out > 0) kz_zero<<<(n_out + 255) / 256, 256>>>(out, n_out);
        return;
    }

    k0_dict  <<<512, dim3(32, 8)>>>(dict, vg, vb, ow);
    k1_proj  <<<dim3(4, 16, 2), 128>>>(query, key, qpe, kpe, wi);
    k1c_gram <<<16, 256>>>();
    k2_ab    <<<dim3(32, 32, 2), 256>>>();
    k3_argmax<<<dim3(VSPL, 4, 16), 256>>>();
    k4_final <<<1024, 64>>>(lg, lb, out, n_out);
}

// round 5
// speedup vs baseline: 1.1669x; 1.1669x over previous
#include <cuda_runtime.h>
#include <math.h>

// Problem constants
#define BSX   2
#define QL    64
#define KLN   64
#define NH    8
#define DKV   64
#define INNER 512
#define VOC   4096
#define NBH   16          // BSX * NH
#define VSPL  16          // v-range splits (256 v each) for argmax kernel

// Masks (all scratch arrays are power-of-2 element counts)
#define M_PROJ 0xFFFFu     // 65536
#define M_DICT 0x3FFFFu    // 262144
#define M_AB   0x3FFFFFu   // 4194304
#define M_NRM  0x3FFu      // 1024
#define M_G    0xFFFFu     // 65536
#define M_P    0xFFFFFu    // 1048576

// ---------------- scratch (device globals; no allocation allowed) -------------
__device__ float g_qproj[BSX * QL * INNER];        // [b][q][e]       65536
__device__ float g_kproj[BSX * KLN * INNER];       // [b][k][e]       65536
__device__ float g_dn[VOC * DKV];                  // l2-norm dict    262144
__device__ float g_dp[VOC * DKV];                  // LN(dict)@O      262144
__device__ float g_A[NBH * QL * VOC];              // [bh][q][v]      4194304
__device__ float g_Bm[NBH * KLN * VOC];            // [bh][k][v]      4194304
__device__ float g_nq[NBH * QL];                   // ||qp||^2        1024
__device__ float g_nk[NBH * KLN];                  //                 1024
__device__ float g_G[NBH * QL * KLN];              // <qp,kp>         65536
__device__ float g_pv[NBH * QL * KLN * VSPL];      // partial max     1048576
__device__ int   g_pi[NBH * QL * KLN * VSPL];      // partial argidx  1048576

// ---------------- K0: dict preprocessing (l2norm + LN@O) ----------------------
__global__ void k0_dict(const float* __restrict__ dict,
                        const float* __restrict__ vg,
                        const float* __restrict__ vb,
                        const float* __restrict__ O) {
    int l = threadIdx.x;                               // 0..31
    int r = blockIdx.x * blockDim.y + threadIdx.y;     // 0..4095
    float x0 = dict[(r * DKV + l) & M_DICT];
    float x1 = dict[(r * DKV + 32 + l) & M_DICT];

    float s = x0 * x0 + x1 * x1;
    #pragma unroll
    for (int o = 16; o > 0; o >>= 1) s += __shfl_xor_sync(0xffffffffu, s, o);
    float inv = rsqrtf(fmaxf(s, 1e-12f));
    g_dn[(r * DKV + l) & M_DICT]      = x0 * inv;
    g_dn[(r * DKV + 32 + l) & M_DICT] = x1 * inv;

    float m = x0 + x1;
    #pragma unroll
    for (int o = 16; o > 0; o >>= 1) m += __shfl_xor_sync(0xffffffffu, m, o);
    m *= (1.0f / 64.0f);
    float d0 = x0 - m, d1 = x1 - m;
    float v = d0 * d0 + d1 * d1;
    #pragma unroll
    for (int o = 16; o > 0; o >>= 1) v += __shfl_xor_sync(0xffffffffu, v, o);
    v *= (1.0f / 64.0f);
    float rs = rsqrtf(v + 1e-6f);
    float ln0 = d0 * rs * vg[l & 63]      + vb[l & 63];
    float ln1 = d1 * rs * vg[(l + 32) & 63] + vb[(l + 32) & 63];

    float a0 = 0.f, a1 = 0.f;
    #pragma unroll
    for (int d2 = 0; d2 < 32; d2++) {
        float t = __shfl_sync(0xffffffffu, ln0, d2);
        a0 += t * O[(d2 * 64 + l) & 4095];
        a1 += t * O[(d2 * 64 + 32 + l) & 4095];
    }
    #pragma unroll
    for (int d2 = 0; d2 < 32; d2++) {
        float t = __shfl_sync(0xffffffffu, ln1, d2);
        a0 += t * O[((32 + d2) * 64 + l) & 4095];
        a1 += t * O[((32 + d2) * 64 + 32 + l) & 4095];
    }
    g_dp[(r * DKV + l) & M_DICT]      = a0;
    g_dp[(r * DKV + 32 + l) & M_DICT] = a1;
}

// ---------------- K1: q_proj / k_proj GEMM ------------------------------------
__global__ void k1_proj(const float* __restrict__ q, const float* __restrict__ k,
                        const float* __restrict__ qpe, const float* __restrict__ kpe,
                        const float* __restrict__ wi) {
    __shared__ float xs[8][INNER];
    int side = blockIdx.z;
    const float* xin = side ? k   : q;
    const float* pin = side ? kpe : qpe;
    const float* W   = wi + side * (INNER * INNER);
    float* out = side ? g_kproj : g_qproj;
    int m0 = blockIdx.y * 8;
    int tid = threadIdx.x;                             // 128 threads
    for (int i = tid; i < 8 * INNER; i += 128) {
        int r = i >> 9, d = i & 511;
        int gidx = ((m0 + r) * INNER + d) & M_PROJ;
        xs[r][d] = xin[gidx] + pin[gidx];
    }
    __syncthreads();
    int e = blockIdx.x * 128 + tid;                    // 0..511
    float acc[8] = {};
    for (int d = 0; d < INNER; d += 2) {
        float w0 = W[((d + 0) * INNER + e) & 0x3FFFF];
        float w1 = W[((d + 1) * INNER + e) & 0x3FFFF];
        #pragma unroll
        for (int r = 0; r < 8; r++) {
            acc[r] += xs[r][d] * w0 + xs[r][d + 1] * w1;
        }
    }
    #pragma unroll
    for (int r = 0; r < 8; r++)
        out[((m0 + r) * INNER + e) & M_PROJ] = acc[r];
}

// ---------------- K1c: per-head Gram matrix + row norms -----------------------
__global__ void k1c_gram() {
    __shared__ float qs[64][65];
    __shared__ float ks[64][65];
    int bh = blockIdx.x;                               // 0..15
    int b = bh >> 3, h = bh & 7;
    int tid = threadIdx.x;                             // 256
    for (int i = tid; i < 4096; i += 256) {
        int r = i >> 6, d = i & 63;
        qs[r][d] = g_qproj[((b * 64 + r) * INNER + h * 64 + d) & M_PROJ];
        ks[r][d] = g_kproj[((b * 64 + r) * INNER + h * 64 + d) & M_PROJ];
    }
    __syncthreads();
    int qq = tid >> 2;
    int kb = (tid & 3) * 16;
    float acc[16] = {};
    for (int d = 0; d < 64; d++) {
        float a = qs[qq][d];
        #pragma unroll
        for (int j = 0; j < 16; j++) acc[j] += a * ks[kb + j][d];
    }
    #pragma unroll
    for (int j = 0; j < 16; j++)
        g_G[((bh * 64 + qq) * 64 + kb + j) & M_G] = acc[j];
    if (tid < 64) {
        float s = 0.f;
        #pragma unroll 8
        for (int d = 0; d < 64; d++) { float x = qs[tid][d]; s += x * x; }
        g_nq[(bh * 64 + tid) & M_NRM] = s;
    } else if (tid < 128) {
        int r = tid - 64;
        float s = 0.f;
        #pragma unroll 8
        for (int d = 0; d < 64; d++) { float x = ks[r][d]; s += x * x; }
        g_nk[(bh * 64 + r) & M_NRM] = s;
    }
}

// ---------------- K2: A = qp_head @ d_n^T, B = kp_head @ d_n^T ----------------
// block tile: 64 rows x 128 v; per-thread 4 rows x 8 v; 256 threads
__global__ void k2_ab() {
    __shared__ float xs[64][68];                       // [row][d], 272B rows
    __shared__ float dst[64][132];                     // [d][v] transposed
    int side = blockIdx.z;
    int bh = blockIdx.y;                               // 0..15
    int b = bh >> 3, h = bh & 7;
    int v0 = blockIdx.x * 128;
    const float* xin = side ? g_kproj : g_qproj;
    float* out = side ? g_Bm : g_A;
    int tid = threadIdx.x;                             // 256

    // fill xs (64 rows x 64 d), float4 loads+stores
    for (int i = tid; i < 64 * 16; i += 256) {
        int r = i >> 4, d4 = (i & 15) * 4;
        int g = ((b * 64 + r) * INNER + h * 64 + d4) & (M_PROJ & ~3u);
        float4 vv = *(const float4*)&xin[g];
        *(float4*)&xs[r][d4] = vv;
    }
    // fill dst (transpose dict tile: 128 v x 64 d -> [d][v])
    for (int i = tid; i < 128 * 16; i += 256) {
        int vl = i >> 4, d4 = (i & 15) * 4;
        int g = ((v0 + vl) * DKV + d4) & (M_DICT & ~3u);
        float4 vv = *(const float4*)&g_dn[g];
        dst[d4 + 0][vl] = vv.x; dst[d4 + 1][vl] = vv.y;
        dst[d4 + 2][vl] = vv.z; dst[d4 + 3][vl] = vv.w;
    }
    __syncthreads();

    int tv = tid & 15, tr = tid >> 4;                  // 16 v-groups x 16 row-groups
    float acc[4][8] = {};
    #pragma unroll 4
    for (int d = 0; d < 64; d++) {
        float4 dv0 = *(float4*)&dst[d][tv * 8];
        float4 dv1 = *(float4*)&dst[d][tv * 8 + 4];
        #pragma unroll
        for (int i = 0; i < 4; i++) {
            float a = xs[tr * 4 + i][d];
            acc[i][0] += a * dv0.x; acc[i][1] += a * dv0.y;
            acc[i][2] += a * dv0.z; acc[i][3] += a * dv0.w;
            acc[i][4] += a * dv1.x; acc[i][5] += a * dv1.y;
            acc[i][6] += a * dv1.z; acc[i][7] += a * dv1.w;
        }
    }
    #pragma unroll
    for (int i = 0; i < 4; i++) {
        int row = tr * 4 + i;
        int base = ((bh * 64 + row) * VOC + v0 + tv * 8) & (M_AB & ~3u);
        *(float4*)&out[base]     = make_float4(acc[i][0], acc[i][1], acc[i][2], acc[i][3]);
        *(float4*)&out[base + 4] = make_float4(acc[i][4], acc[i][5], acc[i][6], acc[i][7]);
    }
}

// ---------------- K3: partial argmax_v (A[q,v] + B[k,v]) ----------------------
// one block per (bh, v-split of 256); per-thread 4q x 4k; 256 threads
__global__ void k3_argmax() {
    __shared__ float As[64][67];                       // odd stride: bank-safe
    __shared__ float Bs[64][67];
    int vs = blockIdx.x;                               // 0..15
    int bh = blockIdx.y;                               // 0..15
    int tid = threadIdx.x;                             // 256
    int tq = tid & 15, tk = tid >> 4;
    float best[4][4];
    int   bidx[4][4];
    #pragma unroll
    for (int i = 0; i < 4; i++)
        #pragma unroll
        for (int j = 0; j < 4; j++) { best[i][j] = -3.402823466e38f; bidx[i][j] = 0; }

    for (int sc = 0; sc < 4; sc++) {
        int vb = vs * 256 + sc * 64;
        __syncthreads();
        for (int i = tid; i < 4096; i += 256) {
            int r = i >> 6, v = i & 63;
            As[r][v] = g_A [((bh * 64 + r) * VOC + vb + v) & M_AB];
            Bs[r][v] = g_Bm[((bh * 64 + r) * VOC + vb + v) & M_AB];
        }
        __syncthreads();
        #pragma unroll 2
        for (int v = 0; v < 64; v++) {
            float a[4], bb[4];
            #pragma unroll
            for (int i = 0; i < 4; i++) {
                a[i]  = As[tq + 16 * i][v];
                bb[i] = Bs[tk + 16 * i][v];
            }
            int gi = vb + v;
            #pragma unroll
            for (int i = 0; i < 4; i++)
                #pragma unroll
                for (int j = 0; j < 4; j++) {
                    float c = a[i] + bb[j];
                    bool  p = c > best[i][j];
                    best[i][j] = p ? c  : best[i][j];
                    bidx[i][j] = p ? gi : bidx[i][j];
                }
        }
    }
    #pragma unroll
    for (int i = 0; i < 4; i++)
        #pragma unroll
        for (int j = 0; j < 4; j++) {
            int q = tq + 16 * i, kk = tk + 16 * j;
            int pair = (bh * 64 + q) * 64 + kk;
            g_pv[(pair * VSPL + vs) & M_P] = best[i][j];
            g_pi[(pair * VSPL + vs) & M_P] = bidx[i][j];
        }
}

// ---------------- K4: merge partials + scores/ids + weighted sum + final LN ---
__global__ void k4_final(const float* __restrict__ lng, const float* __restrict__ lnb,
                         float* __restrict__ out, int n_out) {
    __shared__ float sws[64];
    __shared__ int   sid[64];
    __shared__ float sred[64];
    int idx = blockIdx.x;                              // 0..1023 = (b,q,h)
    int b = idx >> 9, q = (idx >> 3) & 63, h = idx & 7;
    int bh = b * 8 + h;
    int t = threadIdx.x;                               // 64
    int kk = t;
    int pair = (bh * 64 + q) * 64 + kk;
    float bv = -3.402823466e38f; int bi = 0;
    #pragma unroll
    for (int p = 0; p < VSPL; p++) {                   // ascending v-order: first-max
        float v = g_pv[(pair * VSPL + p) & M_P];
        if (v > bv) { bv = v; bi = g_pi[(pair * VSPL + p) & M_P]; }
    }
    float n2 = g_nq[(bh * 64 + q) & M_NRM] + g_nk[(bh * 64 + kk) & M_NRM]
             + 2.0f * g_G[((bh * 64 + q) * 64 + kk) & M_G];
    float ws = bv * rsqrtf(fmaxf(n2, 1e-12f));
    int oidx = ((b * 64 + q) * 64 + kk) * 8 + h;
    if (65536 + oidx < n_out)  out[65536  + oidx] = (float)bi;  // out_ids
    if (131072 + oidx < n_out) out[131072 + oidx] = ws;         // r3_scores
    sws[t] = ws; sid[t] = bi;
    __syncthreads();
    int e = t;
    float acc = 0.f;
    #pragma unroll 4
    for (int j = 0; j < 64; j++)
        acc += sws[j] * g_dp[(sid[j] * DKV + e) & M_DICT];
    acc *= (1.0f / 64.0f);
    sred[t] = acc; __syncthreads();
    #pragma unroll
    for (int s = 32; s > 0; s >>= 1) { if (t < s) sred[t] += sred[t + s]; __syncthreads(); }
    float mean = sred[0] * (1.0f / 64.0f);
    __syncthreads();
    float diff = acc - mean;
    sred[t] = diff * diff; __syncthreads();
    #pragma unroll
    for (int s = 32; s > 0; s >>= 1) { if (t < s) sred[t] += sred[t + s]; __syncthreads(); }
    float var = sred[0] * (1.0f / 64.0f);
    float r = diff * rsqrtf(var + 1e-6f) * lng[e & 63] + lnb[e & 63];
    int widx = (bh * 64 + q) * 64 + e;
    if (widx < n_out) out[widx] = r;                   // [b][h][q][e]
}

// ---------------- fallback: zero-fill output (diagnostic, never crashes) ------
__global__ void kz_zero(float* __restrict__ out, int n_out) {
    int i = blockIdx.x * 256 + threadIdx.x;
    if (i < n_out) out[i] = 0.0f;
}

// ---------------- launch ------------------------------------------------------
static bool size_ok(int got, int need_elems) {
    return got == need_elems || got == need_elems * 4;   // elements or bytes
}

extern "C" void kernel_launch(void* const* d_in, const int* in_sizes, int n_in,
                              void* d_out, int out_size) {
    int n_out = out_size;
    if (n_out == 65536 * 4 || n_out == 196608 * 4) n_out >>= 2;
    if (n_out < 0) n_out = 0;
    float* out = (float*)d_out;

    const int SZ_BIG = BSX * QL * INNER;       // 65536
    const int SZ_WI  = 2 * INNER * INNER;      // 524288
    const int SZ_DI  = VOC * DKV;              // 262144
    const int SZ_OW  = DKV * DKV;              // 4096
    const int SZ_V   = DKV;                    // 64

    const float *query = 0, *key = 0, *qpe = 0, *kpe = 0, *wi = 0, *dict = 0,
                *ow = 0, *vg = 0, *vb = 0, *lg = 0, *lb = 0;
    bool mapped = false;

    if (n_in >= 11) {
        const int sig[11] = {SZ_BIG, SZ_BIG, SZ_BIG, SZ_BIG, SZ_WI, SZ_DI,
                             SZ_V, SZ_V, SZ_OW, SZ_V, SZ_V};
        bool ok = true;
        for (int i = 0; i < 11; i++) ok = ok && size_ok(in_sizes[i], sig[i]);
        if (ok) {
            query = (const float*)d_in[0];  key = (const float*)d_in[1];
            qpe   = (const float*)d_in[2];  kpe = (const float*)d_in[3];
            wi    = (const float*)d_in[4];  dict = (const float*)d_in[5];
            vg    = (const float*)d_in[6];  vb  = (const float*)d_in[7];
            ow    = (const float*)d_in[8];  lg  = (const float*)d_in[9];
            lb    = (const float*)d_in[10];
            mapped = true;
        }
        if (!mapped) {
            const int alp[11] = {SZ_BIG, SZ_BIG, SZ_V, SZ_V, SZ_BIG, SZ_BIG,
                                 SZ_DI, SZ_V, SZ_V, SZ_OW, SZ_WI};
            bool ok2 = true;
            for (int i = 0; i < 11; i++) ok2 = ok2 && size_ok(in_sizes[i], alp[i]);
            if (ok2) {
                key  = (const float*)d_in[0];  kpe = (const float*)d_in[1];
                lb   = (const float*)d_in[2];  lg  = (const float*)d_in[3];
                qpe  = (const float*)d_in[4];  query = (const float*)d_in[5];
                dict = (const float*)d_in[6];  vb  = (const float*)d_in[7];
                vg   = (const float*)d_in[8];  ow  = (const float*)d_in[9];
                wi   = (const float*)d_in[10];
                mapped = true;
            }
        }
    }

    if (!mapped) {
        if (n_out > 0) kz_zero<<<(n_out + 255) / 256, 256>>>(out, n_out);
        return;
    }

    k0_dict  <<<512, dim3(32, 8)>>>(dict, vg, vb, ow);
    k1_proj  <<<dim3(4, 16, 2), 128>>>(query, key, qpe, kpe, wi);
    k1c_gram <<<16, 256>>>();
    k2_ab    <<<dim3(32, 16, 2), 256>>>();
    k3_argmax<<<dim3(VSPL, 16), 256>>>();
    k4_final <<<1024, 64>>>(lg, lb, out, n_out);
}